// round 5
// baseline (speedup 1.0000x reference)
#include <cuda_runtime.h>

#define DT    0.04f
#define DT2   (0.04f * 0.04f * 0.5f)
#define AXM   9.0f
#define PDM   1.244f
#define SPM   20.0f

#define BLK     128      // threads per block = trajectories per block
#define TCHUNK  8        // time steps per tile
#define NTILE   (128 / TCHUNK)          // 16
#define IN_F4   (TCHUNK * 2 / 4)        // 4 float4 motion / traj / tile
#define OUT_F4  (TCHUNK)                // 8 float4 output / traj / tile
#define IN_PITCH  5                     // conflict-free pad
#define OUT_PITCH 9

__device__ __forceinline__ void step(float& x, float& y, float& v, float& psi,
                                     float m0, float m1) {
    float ax = fminf(fmaxf(m0, -AXM), AXM);
    float pd = fminf(fmaxf(m1, -PDM), PDM);
    float sn, cs;
    __sincosf(psi, &sn, &cs);
    x = fmaf(v * cs, DT, fmaf(fmaf(ax, cs, -pd * v * sn), DT2, x));
    y = fmaf(v * sn, DT, fmaf(fmaf(ax, sn,  pd * v * cs), DT2, y));
    v = fminf(fmaxf(fmaf(ax, DT, v), -SPM), SPM);
    psi = fmaf(pd, DT, psi);
}

__global__ __launch_bounds__(BLK, 8)   // force <=64 regs -> 8 CTAs/SM
void kin_kernel(const float4* __restrict__ motion,   // [B,128,2] = 64 f4/traj
                const float4* __restrict__ init,     // [B,4]
                float4* __restrict__ out)            // [B,128,4] = 128 f4/traj
{
    __shared__ float4 s_in [BLK][IN_PITCH];    // 10 KiB
    __shared__ float4 s_out[BLK][OUT_PITCH];   // 18 KiB

    const int tid = threadIdx.x;
    const int b0  = blockIdx.x * BLK;

    float4 s = init[b0 + tid];
    float x = s.x, y = s.y, v = s.z, psi = s.w;

    // staging coordinates (fixed across tiles)
    const int irow = tid >> 2, icol = tid & 3;               // input: 4 lanes/traj
    const int orow = tid >> 3, ocol = tid & 7;               // drain: 8 lanes/traj
    const float4* mbase = motion + (size_t)b0 * 64;
    float4*       obase = out    + (size_t)b0 * 128;

    // preload tile 0 (coalesced LDG.128)
    float4 r_in[IN_F4];
    #pragma unroll
    for (int k = 0; k < IN_F4; k++)
        r_in[k] = mbase[(size_t)(irow + k * 32) * 64 + icol];

    #pragma unroll 1
    for (int tile = 0; tile < NTILE; tile++) {
        // commit staged registers to smem
        #pragma unroll
        for (int k = 0; k < IN_F4; k++)
            s_in[irow + k * 32][icol] = r_in[k];
        __syncthreads();   // s_in ready; prior drain of s_out complete

        // prefetch next tile (overlaps compute)
        if (tile + 1 < NTILE) {
            #pragma unroll
            for (int k = 0; k < IN_F4; k++)
                r_in[k] = mbase[(size_t)(irow + k * 32) * 64 + (tile + 1) * IN_F4 + icol];
        }

        // compute 8 steps, stage results
        #pragma unroll
        for (int j = 0; j < IN_F4; j++) {
            float4 mp = s_in[tid][j];
            step(x, y, v, psi, mp.x, mp.y);
            s_out[tid][2 * j]     = make_float4(x, y, v, psi);
            step(x, y, v, psi, mp.z, mp.w);
            s_out[tid][2 * j + 1] = make_float4(x, y, v, psi);
        }
        __syncthreads();   // s_out ready

        // drain: fully coalesced STG.128 (full 128B lines)
        #pragma unroll
        for (int k = 0; k < OUT_F4; k++)
            obase[(size_t)(orow + k * 16) * 128 + tile * OUT_F4 + ocol] =
                s_out[orow + k * 16][ocol];
        // next tile's first __syncthreads orders drain vs s_in/s_out reuse
    }
}

extern "C" void kernel_launch(void* const* d_in, const int* in_sizes, int n_in,
                              void* d_out, int out_size) {
    const float4* motion = (const float4*)d_in[0];
    const float4* init   = (const float4*)d_in[1];
    float4*       out    = (float4*)d_out;

    int B = in_sizes[1] / 4;          // 262144
    int blocks = B / BLK;             // 2048
    kin_kernel<<<blocks, BLK>>>(motion, init, out);
}

// round 7
// speedup vs baseline: 1.0096x; 1.0096x over previous
#include <cuda_runtime.h>

#define DT    0.04f
#define DT2   (0.04f * 0.04f * 0.5f)
#define AXM   9.0f
#define PDM   1.244f
#define SPM   20.0f

#define BLK     128
#define NW      (BLK / 32)              // 4 warps, each owns 32 trajectories
#define TCHUNK  8
#define NTILE   (128 / TCHUNK)          // 16
#define IN_F4   4                       // float4 motion / traj / tile
#define OUT_F4  8                       // float4 output / traj / tile
#define IN_PITCH  5
#define OUT_PITCH 9

__device__ __forceinline__ void step(float& x, float& y, float& v, float& psi,
                                     float m0, float m1) {
    float ax = fminf(fmaxf(m0, -AXM), AXM);
    float pd = fminf(fmaxf(m1, -PDM), PDM);
    float sn, cs;
    __sincosf(psi, &sn, &cs);
    x = fmaf(v * cs, DT, fmaf(fmaf(ax, cs, -pd * v * sn), DT2, x));
    y = fmaf(v * sn, DT, fmaf(fmaf(ax, sn,  pd * v * cs), DT2, y));
    v = fminf(fmaxf(fmaf(ax, DT, v), -SPM), SPM);
    psi = fmaf(pd, DT, psi);
}

__global__ __launch_bounds__(BLK)      // no reg cap — R5 showed capping hurts
void kin_kernel(const float4* __restrict__ motion,   // [B,128,2] = 64 f4/traj
                const float4* __restrict__ init,     // [B,4]
                float4* __restrict__ out)            // [B,128,4] = 128 f4/traj
{
    // warp-private slabs: all staging is warp-internal -> __syncwarp only
    __shared__ float4 s_in [NW][32][IN_PITCH];    // 10 KiB
    __shared__ float4 s_out[NW][32][OUT_PITCH];   // 18 KiB

    const int w    = threadIdx.x >> 5;
    const int lane = threadIdx.x & 31;
    const int b0   = blockIdx.x * BLK + w * 32;   // this warp's 32 trajectories

    float4 s = init[b0 + lane];
    float x = s.x, y = s.y, v = s.z, psi = s.w;

    const int irow = lane >> 2, icol = lane & 3;  // input staging: 4 lanes/traj
    const int orow = lane >> 3, ocol = lane & 7;  // drain: 8 lanes/traj
    const float4* mbase = motion + (size_t)b0 * 64;
    float4*       obase = out    + (size_t)b0 * 128;

    // preload tile 0 (coalesced LDG.128, 64B per traj row)
    float4 r_in[IN_F4];
    #pragma unroll
    for (int k = 0; k < IN_F4; k++)
        r_in[k] = mbase[(size_t)(irow + k * 8) * 64 + icol];

    #pragma unroll 1
    for (int tile = 0; tile < NTILE; tile++) {
        // commit staged registers to this warp's s_in slab
        #pragma unroll
        for (int k = 0; k < IN_F4; k++)
            s_in[w][irow + k * 8][icol] = r_in[k];
        __syncwarp();

        // prefetch next tile (overlaps compute; 4 outstanding LDG.128)
        if (tile + 1 < NTILE) {
            #pragma unroll
            for (int k = 0; k < IN_F4; k++)
                r_in[k] = mbase[(size_t)(irow + k * 8) * 64 + (tile + 1) * IN_F4 + icol];
        }

        // compute 8 steps from own smem row, stage results
        #pragma unroll
        for (int j = 0; j < IN_F4; j++) {
            float4 mp = s_in[w][lane][j];
            step(x, y, v, psi, mp.x, mp.y);
            s_out[w][lane][2 * j]     = make_float4(x, y, v, psi);
            step(x, y, v, psi, mp.z, mp.w);
            s_out[w][lane][2 * j + 1] = make_float4(x, y, v, psi);
        }
        __syncwarp();

        // drain: 8 iterations, each a fully-coalesced 4x128B-line STG burst
        #pragma unroll
        for (int k = 0; k < OUT_F4; k++)
            obase[(size_t)(orow + k * 4) * 128 + tile * OUT_F4 + ocol] =
                s_out[w][orow + k * 4][ocol];
        __syncwarp();   // protect s_in/s_out reuse next tile
    }
}

extern "C" void kernel_launch(void* const* d_in, const int* in_sizes, int n_in,
                              void* d_out, int out_size) {
    const float4* motion = (const float4*)d_in[0];
    const float4* init   = (const float4*)d_in[1];
    float4*       out    = (float4*)d_out;

    int B = in_sizes[1] / 4;          // 262144
    int blocks = B / BLK;             // 2048
    kin_kernel<<<blocks, BLK>>>(motion, init, out);
}

// round 11
// speedup vs baseline: 1.2856x; 1.2734x over previous
#include <cuda_runtime.h>
#include <cstdint>

#define DT    0.04f
#define DT2   (0.04f * 0.04f * 0.5f)
#define AXM   9.0f
#define PDM   1.244f
#define SPM   20.0f

#define BLK     128      // threads per block = trajectories per block
#define TCHUNK  8        // time steps per tile
#define NTILE   (128 / TCHUNK)          // 16
#define IN_F4   4                       // float4 motion / traj / tile
#define OUT_F4  8                       // float4 output / traj / tile
#define IN_PITCH  5                     // conflict-free pads (audited)
#define OUT_PITCH 9

__device__ __forceinline__ void cp_async16(void* smem_dst, const void* gmem_src) {
    uint32_t s = (uint32_t)__cvta_generic_to_shared(smem_dst);
    asm volatile("cp.async.cg.shared.global [%0], [%1], 16;\n" :: "r"(s), "l"(gmem_src));
}
__device__ __forceinline__ void cp_async_commit() {
    asm volatile("cp.async.commit_group;\n" ::: "memory");
}
__device__ __forceinline__ void cp_async_wait1() {
    asm volatile("cp.async.wait_group 1;\n" ::: "memory");
}

__device__ __forceinline__ void step(float& x, float& y, float& v, float& psi,
                                     float m0, float m1) {
    float ax = fminf(fmaxf(m0, -AXM), AXM);
    float pd = fminf(fmaxf(m1, -PDM), PDM);
    float sn, cs;
    __sincosf(psi, &sn, &cs);
    x = fmaf(v * cs, DT, fmaf(fmaf(ax, cs, -pd * v * sn), DT2, x));
    y = fmaf(v * sn, DT, fmaf(fmaf(ax, sn,  pd * v * cs), DT2, y));
    v = fminf(fmaxf(fmaf(ax, DT, v), -SPM), SPM);
    psi = fmaf(pd, DT, psi);
}

__global__ __launch_bounds__(BLK)      // no reg cap (R5 lesson)
void kin_kernel(const float4* __restrict__ motion,   // [B,128,2] = 64 f4/traj
                const float4* __restrict__ init,     // [B,4]
                float4* __restrict__ out)            // [B,128,4] = 128 f4/traj
{
    __shared__ float4 s_in [2][BLK][IN_PITCH];    // 20 KiB, double-buffered (cp.async dst)
    __shared__ float4 s_out[BLK][OUT_PITCH];      // 18 KiB

    const int tid = threadIdx.x;
    const int b0  = blockIdx.x * BLK;

    float4 s = init[b0 + tid];
    float x = s.x, y = s.y, v = s.z, psi = s.w;

    const int irow = tid >> 2, icol = tid & 3;    // staging: 4 lanes/traj
    const int orow = tid >> 3, ocol = tid & 7;    // drain:   8 lanes/traj
    const float4* mbase = motion + (size_t)b0 * 64;
    float4*       obase = out    + (size_t)b0 * 128;

    // prologue: fill stages 0 and 1 with tiles 0 and 1 (two cp.async groups)
    #pragma unroll
    for (int k = 0; k < IN_F4; k++)
        cp_async16(&s_in[0][irow + k * 32][icol],
                   &mbase[(size_t)(irow + k * 32) * 64 + icol]);
    cp_async_commit();
    #pragma unroll
    for (int k = 0; k < IN_F4; k++)
        cp_async16(&s_in[1][irow + k * 32][icol],
                   &mbase[(size_t)(irow + k * 32) * 64 + IN_F4 + icol]);
    cp_async_commit();

    #pragma unroll 1
    for (int tile = 0; tile < NTILE; tile++) {
        const int st = tile & 1;

        // fill(tile) complete (<=1 group may remain outstanding)
        cp_async_wait1();
        __syncthreads();

        // compute 8 steps from own smem row, stage results
        #pragma unroll
        for (int j = 0; j < IN_F4; j++) {
            float4 mp = s_in[st][tid][j];
            step(x, y, v, psi, mp.x, mp.y);
            s_out[tid][2 * j]     = make_float4(x, y, v, psi);
            step(x, y, v, psi, mp.z, mp.w);
            s_out[tid][2 * j + 1] = make_float4(x, y, v, psi);
        }
        __syncthreads();   // s_out ready; all reads of s_in[st] done

        // refill freed stage with tile+2 (always commit to keep group count uniform)
        if (tile + 2 < NTILE) {
            #pragma unroll
            for (int k = 0; k < IN_F4; k++)
                cp_async16(&s_in[st][irow + k * 32][icol],
                           &mbase[(size_t)(irow + k * 32) * 64 + (tile + 2) * IN_F4 + icol]);
        }
        cp_async_commit();

        // drain: fully coalesced STG.128 (full 128B lines), streaming hint
        #pragma unroll
        for (int k = 0; k < OUT_F4; k++)
            __stcs(&obase[(size_t)(orow + k * 16) * 128 + tile * OUT_F4 + ocol],
                   s_out[orow + k * 16][ocol]);
        __syncthreads();   // drain reads done before s_out rewritten
    }
}

extern "C" void kernel_launch(void* const* d_in, const int* in_sizes, int n_in,
                              void* d_out, int out_size) {
    const float4* motion = (const float4*)d_in[0];
    const float4* init   = (const float4*)d_in[1];
    float4*       out    = (float4*)d_out;

    int B = in_sizes[1] / 4;          // 262144
    int blocks = B / BLK;             // 2048
    kin_kernel<<<blocks, BLK>>>(motion, init, out);
}